// round 2
// baseline (speedup 1.0000x reference)
#include <cuda_runtime.h>
#include <math.h>

#define NT   8192
#define NO   8192
#define FIN  256
#define FOUT 64
#define ALPHA 0.2f

#define BM 64
#define BK 32

// scratch (device globals — no allocation allowed)
__device__ float g_wtv[FIN];
__device__ float g_wov[FIN];
__device__ float g_et[NT];
__device__ float g_eo[NO];
__device__ float g_ho[NO * FOUT];
__device__ float g_eomax;

// ---------------------------------------------------------------------------
// Prep 1: collapse W_t@a_t and W_o@a_o into 256-vectors. 1 block x 256 thr.
// ---------------------------------------------------------------------------
__global__ void prep_w(const float* __restrict__ Wt,
                       const float* __restrict__ Wo,
                       const float* __restrict__ a) {
    int k = threadIdx.x;  // 0..255
    float s1 = 0.f, s2 = 0.f;
#pragma unroll
    for (int f = 0; f < FOUT; f++) {
        s1 += Wt[k * FOUT + f] * a[f];
        s2 += Wo[k * FOUT + f] * a[FOUT + f];
    }
    g_wtv[k] = s1;
    g_wov[k] = s2;
}

// ---------------------------------------------------------------------------
// Prep 2: e = X @ w  (8192 rows, warp per row). which=0 -> e_t, 1 -> e_o.
// ---------------------------------------------------------------------------
__global__ void prep_e(const float* __restrict__ X, int which) {
    const float* w = which ? g_wov : g_wtv;
    float* o = which ? g_eo : g_et;
    int row = blockIdx.x * 8 + (threadIdx.x >> 5);
    int lane = threadIdx.x & 31;
    const float* x = X + (size_t)row * FIN;
    float s = 0.f;
#pragma unroll
    for (int k = lane; k < FIN; k += 32) s += x[k] * w[k];
#pragma unroll
    for (int off = 16; off; off >>= 1) s += __shfl_xor_sync(0xffffffffu, s, off);
    if (lane == 0) o[row] = s;
}

// ---------------------------------------------------------------------------
// Prep 3: h_o = o_input @ W_o. Block = 4 rows x 64 cols (256 threads).
// ---------------------------------------------------------------------------
__global__ void prep_ho(const float* __restrict__ O, const float* __restrict__ Wo) {
    __shared__ float os[4][FIN];
    int jb = blockIdx.x * 4;
    int t = threadIdx.x;
#pragma unroll
    for (int idx = t; idx < 4 * FIN; idx += 256)
        os[idx / FIN][idx % FIN] = O[(size_t)(jb + idx / FIN) * FIN + (idx % FIN)];
    __syncthreads();
    int r = t >> 6, c = t & 63;
    float s = 0.f;
#pragma unroll 8
    for (int k = 0; k < FIN; k++) s += os[r][k] * Wo[k * FOUT + c];
    g_ho[(size_t)(jb + r) * FOUT + c] = s;
}

// ---------------------------------------------------------------------------
// Prep 4: global max of e_o (shift for stable exp; softmax is shift-invariant
// and lrelu is monotone, so global max >= every row max).
// ---------------------------------------------------------------------------
__global__ void prep_max() {
    __shared__ float sm[1024];
    int t = threadIdx.x;
    float m = -1e30f;
    for (int i = t; i < NO; i += 1024) m = fmaxf(m, g_eo[i]);
    sm[t] = m;
    __syncthreads();
    for (int s = 512; s; s >>= 1) {
        if (t < s) sm[t] = fmaxf(sm[t], sm[t + s]);
        __syncthreads();
    }
    if (t == 0) g_eomax = sm[0];
}

// ---------------------------------------------------------------------------
// Main fused kernel: for a block of BM rows, single pass over all j:
//   p_ij = adj ? exp(lrelu(et_i+eo_j) - m_i) : 0
//   acc  += p * h_o[j][:]  (tiled fp32 GEMM, 4x4 microtiles)
//   l_i  += p
// out = elu(acc / l)
// ---------------------------------------------------------------------------
__global__ __launch_bounds__(256) void attn_main(const int* __restrict__ adj,
                                                 float* __restrict__ out) {
    __shared__ float Ps[BK][BM];     // P transposed: Ps[k][i]
    __shared__ float Hs[BK][FOUT];
    __shared__ float rowl[BM];

    int t = threadIdx.x;
    int ibase = blockIdx.x * BM;

    // P-generation mapping: 4 threads per row, 8 consecutive k each
    int prow = t >> 2;
    int kg = t & 3;
    float et = g_et[ibase + prow];
    float x0 = et + g_eomax;
    float mi = fmaxf(x0, ALPHA * x0);

    // GEMM mapping: 16x16 thread grid, 4x4 microtile
    int tx = t & 15, ty = t >> 4;
    float acc[4][4] = {};

    if (t < BM) rowl[t] = 0.f;
    __syncthreads();

    const int* arow = adj + (size_t)(ibase + prow) * NO + kg * 8;

    for (int jb = 0; jb < NO; jb += BK) {
        // --- load H tile (BK x 64 floats = 2048) ---
        {
            const float4* hp = (const float4*)(g_ho + (size_t)jb * FOUT);
            float4* hs = (float4*)&Hs[0][0];
            hs[t] = hp[t];
            hs[t + 256] = hp[t + 256];
        }
        // --- generate P tile: 8 values per thread ---
        {
            int4 a0 = *(const int4*)(arow + jb);
            int4 a1 = *(const int4*)(arow + jb + 4);
            float4 e0 = *(const float4*)(g_eo + jb + kg * 8);
            float4 e1 = *(const float4*)(g_eo + jb + kg * 8 + 4);
            int av[8] = {a0.x, a0.y, a0.z, a0.w, a1.x, a1.y, a1.z, a1.w};
            float ev[8] = {e0.x, e0.y, e0.z, e0.w, e1.x, e1.y, e1.z, e1.w};
            float ps = 0.f;
#pragma unroll
            for (int q = 0; q < 8; q++) {
                float x = et + ev[q];
                float s = fmaxf(x, ALPHA * x);
                float p = (av[q] > 0) ? __expf(s - mi) : 0.f;
                Ps[kg * 8 + q][prow] = p;
                ps += p;
            }
            // reduce over the 4 consecutive lanes covering this row
            ps += __shfl_xor_sync(0xffffffffu, ps, 1);
            ps += __shfl_xor_sync(0xffffffffu, ps, 2);
            if (kg == 0) rowl[prow] += ps;
        }
        __syncthreads();

        // --- microtiled GEMM: acc += P[BMxBK] @ H[BKx64] ---
#pragma unroll
        for (int k = 0; k < BK; k++) {
            float4 pv = *(const float4*)&Ps[k][ty * 4];
            float4 hv = *(const float4*)&Hs[k][tx * 4];
            float pa[4] = {pv.x, pv.y, pv.z, pv.w};
            float ha[4] = {hv.x, hv.y, hv.z, hv.w};
#pragma unroll
            for (int i = 0; i < 4; i++)
#pragma unroll
                for (int j = 0; j < 4; j++) acc[i][j] += pa[i] * ha[j];
        }
        __syncthreads();
    }

    // --- epilogue: normalize + elu, vectorized store ---
#pragma unroll
    for (int i = 0; i < 4; i++) {
        float inv = 1.f / rowl[ty * 4 + i];
        int orow = ibase + ty * 4 + i;
        float r[4];
#pragma unroll
        for (int j = 0; j < 4; j++) {
            float v = acc[i][j] * inv;
            r[j] = v > 0.f ? v : expm1f(v);
        }
        *(float4*)(out + (size_t)orow * FOUT + tx * 4) =
            make_float4(r[0], r[1], r[2], r[3]);
    }
}

// ---------------------------------------------------------------------------
extern "C" void kernel_launch(void* const* d_in, const int* in_sizes, int n_in,
                              void* d_out, int out_size) {
    const float* t_input = (const float*)d_in[0];
    const float* o_input = (const float*)d_in[1];
    const float* W_t     = (const float*)d_in[2];
    const float* W_o     = (const float*)d_in[3];
    const float* a       = (const float*)d_in[4];
    const int*   adj     = (const int*)d_in[5];
    float* out = (float*)d_out;

    prep_w<<<1, 256>>>(W_t, W_o, a);
    prep_e<<<NT / 8, 256>>>(t_input, 0);
    prep_e<<<NO / 8, 256>>>(o_input, 1);
    prep_ho<<<NO / 4, 256>>>(o_input, W_o);
    prep_max<<<1, 1024>>>();
    attn_main<<<NT / BM, 256>>>(adj, out);
}

// round 6
// speedup vs baseline: 1.7317x; 1.7317x over previous
#include <cuda_runtime.h>
#include <math.h>
#include <cstdint>

#define NT   8192
#define NO   8192
#define FIN  256
#define FOUT 64
#define ALPHA 0.2f

#define KSPLIT 2
#define JPC   (NO / KSPLIT)   // 4096 j per CTA
#define BK    128             // j per tile
#define TILES (JPC / BK)      // 32
#define BM    128             // rows per CTA
#define THREADS 512

// padded smem strides (floats): stride 132 makes (row*132+k)%32 = (4*row+k)%32
// -> conflict-free for the (lane>>2, lane&3) fragment access pattern.
#define PST 132
#define HST 132
#define PS_OFF 0
#define HS_OFF (128 * PST)               // 16896
#define SMEM_FLOATS (HS_OFF + 64 * HST)  // 25344 floats = 101376 B

// ---- scratch ----
__device__ float  g_wtv[FIN], g_wov[FIN];
__device__ float  g_et[NT], g_eo[NO];
__device__ float  g_eomax;
__device__ float2 g_AB[NT];                 // (A_i, B_i)
__device__ float2 g_EF[NO];                 // (E_j, F_j)
__device__ float  g_hoT[FOUT * NO];         // h_o^T, tf32-rounded
__device__ float  g_Dp[KSPLIT * NT * FOUT]; // partial numerators
__device__ float  g_l[KSPLIT * NT];         // partial denominators

__device__ __forceinline__ float to_tf32(float x) {
    uint32_t u;
    asm("cvt.rn.tf32.f32 %0, %1;" : "=r"(u) : "f"(x));
    return __uint_as_float(u);
}

__device__ __forceinline__ void mma_tf32(float* d, const uint32_t* a, const uint32_t* b) {
    asm volatile(
        "mma.sync.aligned.m16n8k8.row.col.f32.tf32.tf32.f32 "
        "{%0,%1,%2,%3}, {%4,%5,%6,%7}, {%8,%9}, {%0,%1,%2,%3};"
        : "+f"(d[0]), "+f"(d[1]), "+f"(d[2]), "+f"(d[3])
        : "r"(a[0]), "r"(a[1]), "r"(a[2]), "r"(a[3]), "r"(b[0]), "r"(b[1]));
}

// ---------------------------------------------------------------------------
// preps
// ---------------------------------------------------------------------------
__global__ void prep_w(const float* __restrict__ Wt, const float* __restrict__ Wo,
                       const float* __restrict__ a) {
    int k = threadIdx.x;
    float s1 = 0.f, s2 = 0.f;
#pragma unroll
    for (int f = 0; f < FOUT; f++) {
        s1 += Wt[k * FOUT + f] * a[f];
        s2 += Wo[k * FOUT + f] * a[FOUT + f];
    }
    g_wtv[k] = s1;
    g_wov[k] = s2;
}

__global__ void prep_e(const float* __restrict__ X, int which) {
    const float* w = which ? g_wov : g_wtv;
    float* o = which ? g_eo : g_et;
    int row = blockIdx.x * 8 + (threadIdx.x >> 5);
    int lane = threadIdx.x & 31;
    const float* x = X + (size_t)row * FIN;
    float s = 0.f;
#pragma unroll
    for (int k = lane; k < FIN; k += 32) s += x[k] * w[k];
#pragma unroll
    for (int off = 16; off; off >>= 1) s += __shfl_xor_sync(0xffffffffu, s, off);
    if (lane == 0) o[row] = s;
}

__global__ void prep_max() {
    __shared__ float sm[1024];
    int t = threadIdx.x;
    float m = -1e30f;
    for (int i = t; i < NO; i += 1024) m = fmaxf(m, g_eo[i]);
    sm[t] = m;
    __syncthreads();
    for (int s = 512; s; s >>= 1) {
        if (t < s) sm[t] = fmaxf(sm[t], sm[t + s]);
        __syncthreads();
    }
    if (t == 0) g_eomax = sm[0];
}

// A_i = exp(et-mi), B_i = exp(0.2*et-mi), mi = lrelu(et+eomax);
// E_j = exp(eo), F_j = exp(0.2*eo).
// p_ij = exp(lrelu(et+eo)-mi) = max(A_i*E_j, B_i*F_j)  (exact: lrelu=max, exp monotone)
__global__ void prep_abef() {
    int i = blockIdx.x * 256 + threadIdx.x;
    float et = g_et[i];
    float x0 = et + g_eomax;
    float mi = fmaxf(x0, ALPHA * x0);
    g_AB[i] = make_float2(expf(et - mi), expf(ALPHA * et - mi));
    float eo = g_eo[i];
    g_EF[i] = make_float2(expf(eo), expf(ALPHA * eo));
}

// h_o^T (tf32-rounded), layout [64][8192]. 32 j-rows per block.
__global__ __launch_bounds__(256) void prep_hoT(const float* __restrict__ O,
                                                const float* __restrict__ Wo) {
    __shared__ float os[32 * FIN];
    int jb = blockIdx.x * 32, t = threadIdx.x;
    const float4* src = (const float4*)(O + (size_t)jb * FIN);
    float4* dst = (float4*)os;
#pragma unroll
    for (int i = 0; i < 8; i++) dst[t + i * 256] = src[t + i * 256];
    __syncthreads();
    int tj = t >> 5, tc = t & 31;
    float acc[4][2] = {};
#pragma unroll 4
    for (int k = 0; k < FIN; k++) {
        float2 w = *(const float2*)(Wo + k * FOUT + tc * 2);
#pragma unroll
        for (int i = 0; i < 4; i++) {
            float o = os[(tj * 4 + i) * FIN + k];
            acc[i][0] += o * w.x;
            acc[i][1] += o * w.y;
        }
    }
#pragma unroll
    for (int ci = 0; ci < 2; ci++) {
        int c = tc * 2 + ci;
        float4 v = make_float4(to_tf32(acc[0][ci]), to_tf32(acc[1][ci]),
                               to_tf32(acc[2][ci]), to_tf32(acc[3][ci]));
        *(float4*)(g_hoT + (size_t)c * NO + jb + tj * 4) = v;
    }
}

// ---------------------------------------------------------------------------
// main: 128 rows x 4096 j per CTA (split-K=2). P built exp-free in smem
// (tf32), P@H via mma.sync m16n8k8 tf32, fp32 register accumulators.
// ---------------------------------------------------------------------------
extern __shared__ float smf[];

__global__ __launch_bounds__(THREADS, 1) void attn_main(const int* __restrict__ adj) {
    float* Ps = smf + PS_OFF;   // [128][PST]
    float* Hs = smf + HS_OFF;   // [64][HST]

    int t = threadIdx.x, w = t >> 5, lane = t & 31;
    int ibase = blockIdx.x * BM;
    int split = blockIdx.y;

    // P-gen mapping: 4 threads per row, 32 consecutive j each
    int row = t >> 2, kg = t & 3;
    float2 AB = g_AB[ibase + row];
    const int* arow = adj + (size_t)(ibase + row) * NO + split * JPC + kg * 32;
    const float2* efr = g_EF + split * JPC + kg * 32;
    const float* hsrc = g_hoT + split * JPC;
    float lsum = 0.f;

    // MMA mapping: warp w -> rows [16*(w>>1), +16), cols [32*(w&1), +32)
    int rbase = 16 * (w >> 1), cbase = 32 * (w & 1);
    int gid = lane >> 2, tid = lane & 3;
    float acc[4][4] = {};

    // prefetch tile 0 adj
    int4 aR[8];
#pragma unroll
    for (int q = 0; q < 8; q++) aR[q] = *(const int4*)(arow + q * 4);

    for (int tile = 0; tile < TILES; tile++) {
        int jb = tile * BK;

        // ---- P tile generation (exp-free) ----
#pragma unroll
        for (int q = 0; q < 8; q++) {
            int4 av = aR[q];
            float4 ef01 = *(const float4*)(efr + jb + q * 4);      // E0,F0,E1,F1
            float4 ef23 = *(const float4*)(efr + jb + q * 4 + 2);  // E2,F2,E3,F3
            float p0 = to_tf32(fmaxf(AB.x * ef01.x, AB.y * ef01.y));
            float p1 = to_tf32(fmaxf(AB.x * ef01.z, AB.y * ef01.w));
            float p2 = to_tf32(fmaxf(AB.x * ef23.x, AB.y * ef23.y));
            float p3 = to_tf32(fmaxf(AB.x * ef23.z, AB.y * ef23.w));
            p0 = __int_as_float(__float_as_int(p0) & (-av.x));
            p1 = __int_as_float(__float_as_int(p1) & (-av.y));
            p2 = __int_as_float(__float_as_int(p2) & (-av.z));
            p3 = __int_as_float(__float_as_int(p3) & (-av.w));
            lsum += (p0 + p1) + (p2 + p3);
            *(float4*)(Ps + row * PST + kg * 32 + q * 4) = make_float4(p0, p1, p2, p3);
        }

        // ---- H tile load: Hs[n][k] <- g_hoT[n][jb+k] ----
#pragma unroll
        for (int i = 0; i < 4; i++) {
            int idx = t + i * 512;          // 2048 float4
            int n = idx >> 5, c4 = idx & 31;
            float4 v = *(const float4*)(hsrc + (size_t)n * NO + jb + c4 * 4);
            *(float4*)(Hs + n * HST + c4 * 4) = v;
        }
        __syncthreads();

        // ---- prefetch next tile's adj (hides DRAM under MMA) ----
        if (tile + 1 < TILES) {
#pragma unroll
            for (int q = 0; q < 8; q++)
                aR[q] = *(const int4*)(arow + (tile + 1) * BK + q * 4);
        }

        // ---- MMA: acc += P[16x128] @ H^T[128x32] ----
#pragma unroll
        for (int kk = 0; kk < 16; kk++) {
            int k0 = kk * 8;
            uint32_t a[4];
            const float* pr = Ps + (rbase + gid) * PST + k0 + tid;
            a[0] = __float_as_uint(pr[0]);
            a[1] = __float_as_uint(pr[8 * PST]);
            a[2] = __float_as_uint(pr[4]);
            a[3] = __float_as_uint(pr[8 * PST + 4]);
#pragma unroll
            for (int nt = 0; nt < 4; nt++) {
                uint32_t b[2];
                const float* hr = Hs + (cbase + 8 * nt + gid) * HST + k0 + tid;
                b[0] = __float_as_uint(hr[0]);
                b[1] = __float_as_uint(hr[4]);
                mma_tf32(acc[nt], a, b);
            }
        }
        __syncthreads();
    }

    // ---- epilogue: partial D and partial l to gmem ----
    float* dp = g_Dp + ((size_t)split * NT + ibase) * FOUT;
#pragma unroll
    for (int nt = 0; nt < 4; nt++) {
        int col = cbase + 8 * nt + 2 * tid;
        *(float2*)(dp + (size_t)(rbase + gid) * FOUT + col) =
            make_float2(acc[nt][0], acc[nt][1]);
        *(float2*)(dp + (size_t)(rbase + gid + 8) * FOUT + col) =
            make_float2(acc[nt][2], acc[nt][3]);
    }
    lsum += __shfl_xor_sync(0xffffffffu, lsum, 1);
    lsum += __shfl_xor_sync(0xffffffffu, lsum, 2);
    if (kg == 0) g_l[split * NT + ibase + row] = lsum;
}

// ---------------------------------------------------------------------------
// combine: out = elu((D0+D1)/(l0+l1))
// ---------------------------------------------------------------------------
__global__ void combine(float* __restrict__ out) {
    int idx = blockIdx.x * 256 + threadIdx.x;  // 131072
    int r = idx >> 4, c4 = idx & 15;
    float4 d0 = *(const float4*)(g_Dp + (size_t)r * FOUT + c4 * 4);
    float4 d1 = *(const float4*)(g_Dp + ((size_t)NT + r) * FOUT + c4 * 4);
    float inv = 1.f / (g_l[r] + g_l[NT + r]);
    float v[4] = {(d0.x + d1.x) * inv, (d0.y + d1.y) * inv,
                  (d0.z + d1.z) * inv, (d0.w + d1.w) * inv};
#pragma unroll
    for (int i = 0; i < 4; i++) v[i] = v[i] > 0.f ? v[i] : expm1f(v[i]);
    *(float4*)(out + (size_t)r * FOUT + c4 * 4) = make_float4(v[0], v[1], v[2], v[3]);
}

// ---------------------------------------------------------------------------
extern "C" void kernel_launch(void* const* d_in, const int* in_sizes, int n_in,
                              void* d_out, int out_size) {
    const float* t_input = (const float*)d_in[0];
    const float* o_input = (const float*)d_in[1];
    const float* W_t     = (const float*)d_in[2];
    const float* W_o     = (const float*)d_in[3];
    const float* a       = (const float*)d_in[4];
    const int*   adj     = (const int*)d_in[5];
    float* out = (float*)d_out;

    cudaFuncSetAttribute(attn_main, cudaFuncAttributeMaxDynamicSharedMemorySize,
                         SMEM_FLOATS * (int)sizeof(float));

    prep_w<<<1, 256>>>(W_t, W_o, a);
    prep_e<<<NT / 8, 256>>>(t_input, 0);
    prep_e<<<NO / 8, 256>>>(o_input, 1);
    prep_max<<<1, 1024>>>();
    prep_abef<<<NT / 256, 256>>>();
    prep_hoT<<<NO / 32, 256>>>(o_input, W_o);
    attn_main<<<dim3(NT / BM, KSPLIT), THREADS,
                SMEM_FLOATS * (int)sizeof(float)>>>(adj);
    combine<<<NT * FOUT / 4 / 256, 256>>>(out);
}

// round 8
// speedup vs baseline: 3.5344x; 2.0410x over previous
#include <cuda_runtime.h>
#include <cuda_bf16.h>
#include <math.h>
#include <cstdint>

#define NT   8192
#define NO   8192
#define FIN  256
#define FOUT 64
#define ALPHA 0.2f

#define KSPLIT 2
#define JPC   (NO / KSPLIT)   // 4096
#define BK    128
#define TILES (JPC / BK)      // 32
#define BM    128
#define THREADS 512

#define PBUF 32768            // 128 rows x 256B (bf16 128k)
#define HBUF 16384            // 64 rows x 256B
#define SM_TOTAL (2 * PBUF + 2 * HBUF)  // 98304

// 16B-chunk swizzle within 128B halves: row r, chunk c (0..15)
#define SWC(r, c) ((((c) & 8) | (((c) ^ (r)) & 7)))

// ---- scratch ----
__device__ float  g_wtv[FIN], g_wov[FIN];
__device__ float  g_et[NT], g_eo[NO];
__device__ unsigned g_eomax_u;
__device__ float2 g_AB[NT];
__device__ float  g_E[NO], g_F[NO];
__device__ __align__(16) __nv_bfloat16 g_hoTb[FOUT * NO];  // h_o^T bf16
__device__ float  g_Dp[KSPLIT * NT * FOUT];
__device__ float  g_l[KSPLIT * NT];

// ---- helpers ----
__device__ __forceinline__ uint32_t smem_u32(const void* p) {
    uint32_t a;
    asm("{ .reg .u64 t; cvta.to.shared.u64 t, %1; cvt.u32.u64 %0, t; }" : "=r"(a) : "l"(p));
    return a;
}
__device__ __forceinline__ uint32_t f2b2(float lo, float hi) {
    __nv_bfloat162 h = __floats2bfloat162_rn(lo, hi);
    return *(uint32_t*)&h;
}
__device__ __forceinline__ unsigned fenc(float x) {
    int s = __float_as_int(x);
    return (s < 0) ? ~(unsigned)s : ((unsigned)s | 0x80000000u);
}
__device__ __forceinline__ float fdec(unsigned u) {
    int s = (u & 0x80000000u) ? (int)(u & 0x7fffffffu) : (int)~u;
    return __int_as_float(s);
}
__device__ __forceinline__ void ldm_x4(uint32_t& r0, uint32_t& r1, uint32_t& r2,
                                       uint32_t& r3, uint32_t addr) {
    asm volatile("ldmatrix.sync.aligned.m8n8.x4.shared.b16 {%0,%1,%2,%3}, [%4];"
                 : "=r"(r0), "=r"(r1), "=r"(r2), "=r"(r3) : "r"(addr));
}
__device__ __forceinline__ void mma_bf16(float* d, uint32_t a0, uint32_t a1,
                                         uint32_t a2, uint32_t a3,
                                         uint32_t b0, uint32_t b1) {
    asm volatile(
        "mma.sync.aligned.m16n8k16.row.col.f32.bf16.bf16.f32 "
        "{%0,%1,%2,%3}, {%4,%5,%6,%7}, {%8,%9}, {%0,%1,%2,%3};"
        : "+f"(d[0]), "+f"(d[1]), "+f"(d[2]), "+f"(d[3])
        : "r"(a0), "r"(a1), "r"(a2), "r"(a3), "r"(b0), "r"(b1));
}

// ---------------------------------------------------------------------------
// preps
// ---------------------------------------------------------------------------
__global__ void prep_w(const float* __restrict__ Wt, const float* __restrict__ Wo,
                       const float* __restrict__ a) {
    int k = threadIdx.x;
    if (k == 0) g_eomax_u = 0u;
    float s1 = 0.f, s2 = 0.f;
#pragma unroll
    for (int f = 0; f < FOUT; f++) {
        s1 += Wt[k * FOUT + f] * a[f];
        s2 += Wo[k * FOUT + f] * a[FOUT + f];
    }
    g_wtv[k] = s1;
    g_wov[k] = s2;
}

// h_o = O @ W_o (fp32) -> g_hoTb (bf16, [64][8192]) and g_eo = h_o @ a_o
__global__ __launch_bounds__(256) void prep_hoT(const float* __restrict__ O,
                                                const float* __restrict__ Wo,
                                                const float* __restrict__ a) {
    __shared__ float os[32 * FIN];
    int jb = blockIdx.x * 32, t = threadIdx.x;
    const float4* src = (const float4*)(O + (size_t)jb * FIN);
    float4* dst = (float4*)os;
#pragma unroll
    for (int i = 0; i < 8; i++) dst[t + i * 256] = src[t + i * 256];
    __syncthreads();
    int tj = t >> 5, tc = t & 31;
    float acc[4][2] = {};
#pragma unroll 4
    for (int k = 0; k < FIN; k++) {
        float2 w = *(const float2*)(Wo + k * FOUT + tc * 2);
#pragma unroll
        for (int i = 0; i < 4; i++) {
            float o = os[(tj * 4 + i) * FIN + k];
            acc[i][0] += o * w.x;
            acc[i][1] += o * w.y;
        }
    }
    // eo = h_o @ a_o (fp32)
    float ao0 = a[FOUT + tc * 2], ao1 = a[FOUT + tc * 2 + 1];
#pragma unroll
    for (int i = 0; i < 4; i++) {
        float e = acc[i][0] * ao0 + acc[i][1] * ao1;
#pragma unroll
        for (int off = 16; off; off >>= 1) e += __shfl_xor_sync(0xffffffffu, e, off);
        if (tc == 0) g_eo[jb + tj * 4 + i] = e;
    }
    // h_o^T in bf16
#pragma unroll
    for (int ci = 0; ci < 2; ci++) {
        int c = tc * 2 + ci;
        uint2 v = make_uint2(f2b2(acc[0][ci], acc[1][ci]),
                             f2b2(acc[2][ci], acc[3][ci]));
        *(uint2*)(g_hoTb + (size_t)c * NO + jb + tj * 4) = v;
    }
}

__global__ void prep_et(const float* __restrict__ X) {
    int row = blockIdx.x * 8 + (threadIdx.x >> 5);
    int lane = threadIdx.x & 31;
    const float* x = X + (size_t)row * FIN;
    float s = 0.f;
#pragma unroll
    for (int k = lane; k < FIN; k += 32) s += x[k] * g_wtv[k];
#pragma unroll
    for (int off = 16; off; off >>= 1) s += __shfl_xor_sync(0xffffffffu, s, off);
    if (lane == 0) g_et[row] = s;
}

__global__ void prep_max() {
    int i = blockIdx.x * 256 + threadIdx.x;
    float m = g_eo[i];
#pragma unroll
    for (int off = 16; off; off >>= 1)
        m = fmaxf(m, __shfl_xor_sync(0xffffffffu, m, off));
    if ((threadIdx.x & 31) == 0) atomicMax(&g_eomax_u, fenc(m));
}

// A=exp(et-mi), B=exp(.2et-mi), mi=lrelu(et+eomax); E=exp(eo), F=exp(.2eo)
// p_ij = exp(lrelu(et+eo)-mi) = max(A*E, B*F)
__global__ void prep_abef() {
    int i = blockIdx.x * 256 + threadIdx.x;
    float eomax = fdec(g_eomax_u);
    float et = g_et[i];
    float x0 = et + eomax;
    float mi = fmaxf(x0, ALPHA * x0);
    g_AB[i] = make_float2(expf(et - mi), expf(ALPHA * et - mi));
    float eo = g_eo[i];
    g_E[i] = expf(eo);
    g_F[i] = expf(ALPHA * eo);
}

// ---------------------------------------------------------------------------
// main
// ---------------------------------------------------------------------------
extern __shared__ char smc[];

__global__ __launch_bounds__(THREADS, 1) void attn_main(const int* __restrict__ adj) {
    const int t = threadIdx.x;
    const int ibase = blockIdx.x * BM;
    const int split = blockIdx.y;
    const uint32_t sb = smem_u32(smc);

    // P-gen mapping: thread = (rg 0..31)x(jg 0..15): rows rg*4..+4, j jg*8..+8
    const int jg = t & 15, rg = t >> 4;
    const int j0 = jg * 8;
    float2 ABr[4];
#pragma unroll
    for (int rr = 0; rr < 4; rr++) ABr[rr] = g_AB[ibase + rg * 4 + rr];
    const int* adjb = adj + (size_t)(ibase + rg * 4) * NO + split * JPC + j0;
    const float* Eb = g_E + split * JPC + j0;
    const float* Fb = g_F + split * JPC + j0;
    float lsum[4] = {0.f, 0.f, 0.f, 0.f};

    // H-load mapping: thread -> row hn, chunks hc and hc+8
    const int hn = t >> 3, hc = t & 7;
    const __nv_bfloat16* hsrc = g_hoTb + (size_t)hn * NO + split * JPC;

    // MMA mapping: warp -> m16 x n32
    const int w = t >> 5, lane = t & 31;
    const int rbase = (w >> 1) * 16, cbase = (w & 1) * 32;
    const int gid = lane >> 2, tid = lane & 3;
    float acc[4][4] = {};

    int4 aC[8];
#pragma unroll
    for (int rr = 0; rr < 4; rr++) {
        aC[2 * rr]     = *(const int4*)(adjb + (size_t)rr * NO);
        aC[2 * rr + 1] = *(const int4*)(adjb + (size_t)rr * NO + 4);
    }

    for (int tile = 0; tile < TILES; tile++) {
        const int jb = tile * BK;
        const int buf = tile & 1;
        char* pB = smc + buf * PBUF;
        char* hB = smc + 2 * PBUF + buf * HBUF;

        // prefetch next adj tile
        if (tile + 1 < TILES) {
            int4 aN[8];
#pragma unroll
            for (int rr = 0; rr < 4; rr++) {
                aN[2 * rr]     = *(const int4*)(adjb + (size_t)rr * NO + jb + BK);
                aN[2 * rr + 1] = *(const int4*)(adjb + (size_t)rr * NO + jb + BK + 4);
            }
            // P-gen for this tile, then rotate
            float4 e0 = *(const float4*)(Eb + jb), e1 = *(const float4*)(Eb + jb + 4);
            float4 f0 = *(const float4*)(Fb + jb), f1 = *(const float4*)(Fb + jb + 4);
#pragma unroll
            for (int rr = 0; rr < 4; rr++) {
                const float A = ABr[rr].x, B = ABr[rr].y;
                int4 a0 = aC[2 * rr], a1 = aC[2 * rr + 1];
                float p0 = fmaxf(A * e0.x, B * f0.x);
                float p1 = fmaxf(A * e0.y, B * f0.y);
                float p2 = fmaxf(A * e0.z, B * f0.z);
                float p3 = fmaxf(A * e0.w, B * f0.w);
                float p4 = fmaxf(A * e1.x, B * f1.x);
                float p5 = fmaxf(A * e1.y, B * f1.y);
                float p6 = fmaxf(A * e1.z, B * f1.z);
                float p7 = fmaxf(A * e1.w, B * f1.w);
                p0 = __int_as_float(__float_as_int(p0) & (-a0.x));
                p1 = __int_as_float(__float_as_int(p1) & (-a0.y));
                p2 = __int_as_float(__float_as_int(p2) & (-a0.z));
                p3 = __int_as_float(__float_as_int(p3) & (-a0.w));
                p4 = __int_as_float(__float_as_int(p4) & (-a1.x));
                p5 = __int_as_float(__float_as_int(p5) & (-a1.y));
                p6 = __int_as_float(__float_as_int(p6) & (-a1.z));
                p7 = __int_as_float(__float_as_int(p7) & (-a1.w));
                lsum[rr] += ((p0 + p1) + (p2 + p3)) + ((p4 + p5) + (p6 + p7));
                uint4 v = make_uint4(f2b2(p0, p1), f2b2(p2, p3),
                                     f2b2(p4, p5), f2b2(p6, p7));
                int r = rg * 4 + rr;
                *(uint4*)(pB + r * 256 + SWC(r, jg) * 16) = v;
            }
#pragma unroll
            for (int q = 0; q < 8; q++) aC[q] = aN[q];
        } else {
            float4 e0 = *(const float4*)(Eb + jb), e1 = *(const float4*)(Eb + jb + 4);
            float4 f0 = *(const float4*)(Fb + jb), f1 = *(const float4*)(Fb + jb + 4);
#pragma unroll
            for (int rr = 0; rr < 4; rr++) {
                const float A = ABr[rr].x, B = ABr[rr].y;
                int4 a0 = aC[2 * rr], a1 = aC[2 * rr + 1];
                float p0 = fmaxf(A * e0.x, B * f0.x);
                float p1 = fmaxf(A * e0.y, B * f0.y);
                float p2 = fmaxf(A * e0.z, B * f0.z);
                float p3 = fmaxf(A * e0.w, B * f0.w);
                float p4 = fmaxf(A * e1.x, B * f1.x);
                float p5 = fmaxf(A * e1.y, B * f1.y);
                float p6 = fmaxf(A * e1.z, B * f1.z);
                float p7 = fmaxf(A * e1.w, B * f1.w);
                p0 = __int_as_float(__float_as_int(p0) & (-a0.x));
                p1 = __int_as_float(__float_as_int(p1) & (-a0.y));
                p2 = __int_as_float(__float_as_int(p2) & (-a0.z));
                p3 = __int_as_float(__float_as_int(p3) & (-a0.w));
                p4 = __int_as_float(__float_as_int(p4) & (-a1.x));
                p5 = __int_as_float(__float_as_int(p5) & (-a1.y));
                p6 = __int_as_float(__float_as_int(p6) & (-a1.z));
                p7 = __int_as_float(__float_as_int(p7) & (-a1.w));
                lsum[rr] += ((p0 + p1) + (p2 + p3)) + ((p4 + p5) + (p6 + p7));
                uint4 v = make_uint4(f2b2(p0, p1), f2b2(p2, p3),
                                     f2b2(p4, p5), f2b2(p6, p7));
                int r = rg * 4 + rr;
                *(uint4*)(pB + r * 256 + SWC(r, jg) * 16) = v;
            }
        }

        // H tile: 16KB, each thread two 16B chunks (coalesced 128B per phase)
        {
            uint4 v0 = *(const uint4*)(hsrc + jb + hc * 8);
            uint4 v1 = *(const uint4*)(hsrc + jb + hc * 8 + 64);
            *(uint4*)(hB + hn * 256 + SWC(hn, hc) * 16) = v0;
            *(uint4*)(hB + hn * 256 + SWC(hn, hc + 8) * 16) = v1;
        }
        __syncthreads();

        // MMA: acc += P[16x128] @ H^T[128x32] per warp, via ldmatrix
        const uint32_t pS = sb + buf * PBUF;
        const uint32_t hS = sb + 2 * PBUF + buf * HBUF;
#pragma unroll
        for (int kk = 0; kk < 8; kk++) {
            uint32_t a0, a1, a2, a3;
            {
                int r = rbase + (lane & 15);
                int c = 2 * kk + (lane >> 4);
                ldm_x4(a0, a1, a2, a3, pS + r * 256 + SWC(r, c) * 16);
            }
            uint32_t b0, b1, b2, b3, b4, b5, b6, b7;
            {
                int g = lane >> 3;
                int n = cbase + (g >> 1) * 8 + (lane & 7);
                int c = 2 * kk + (g & 1);
                uint32_t ad = hS + n * 256 + SWC(n, c) * 16;
                ldm_x4(b0, b1, b2, b3, ad);
                ldm_x4(b4, b5, b6, b7, ad + 16 * 256);
            }
            mma_bf16(acc[0], a0, a1, a2, a3, b0, b1);
            mma_bf16(acc[1], a0, a1, a2, a3, b2, b3);
            mma_bf16(acc[2], a0, a1, a2, a3, b4, b5);
            mma_bf16(acc[3], a0, a1, a2, a3, b6, b7);
        }
        // no second barrier needed: writes(t+1) are post-sync(t); reads(t) are
        // pre-sync(t+1) in every thread's program order.
    }

    // epilogue
    float* dp = g_Dp + ((size_t)split * NT + ibase) * FOUT;
#pragma unroll
    for (int nt = 0; nt < 4; nt++) {
        int col = cbase + nt * 8 + 2 * tid;
        *(float2*)(dp + (size_t)(rbase + gid) * FOUT + col) =
            make_float2(acc[nt][0], acc[nt][1]);
        *(float2*)(dp + (size_t)(rbase + gid + 8) * FOUT + col) =
            make_float2(acc[nt][2], acc[nt][3]);
    }
#pragma unroll
    for (int rr = 0; rr < 4; rr++) {
        float s = lsum[rr];
        s += __shfl_xor_sync(0xffffffffu, s, 1);
        s += __shfl_xor_sync(0xffffffffu, s, 2);
        s += __shfl_xor_sync(0xffffffffu, s, 4);
        s += __shfl_xor_sync(0xffffffffu, s, 8);
        if (jg == 0) g_l[split * NT + ibase + rg * 4 + rr] = s;
    }
}

// ---------------------------------------------------------------------------
__global__ void combine(float* __restrict__ out) {
    int idx = blockIdx.x * 256 + threadIdx.x;
    int r = idx >> 4, c4 = idx & 15;
    float4 d0 = *(const float4*)(g_Dp + (size_t)r * FOUT + c4 * 4);
    float4 d1 = *(const float4*)(g_Dp + ((size_t)NT + r) * FOUT + c4 * 4);
    float inv = 1.f / (g_l[r] + g_l[NT + r]);
    float v[4] = {(d0.x + d1.x) * inv, (d0.y + d1.y) * inv,
                  (d0.z + d1.z) * inv, (d0.w + d1.w) * inv};
#pragma unroll
    for (int i = 0; i < 4; i++) v[i] = v[i] > 0.f ? v[i] : expm1f(v[i]);
    *(float4*)(out + (size_t)r * FOUT + c4 * 4) = make_float4(v[0], v[1], v[2], v[3]);
}

// ---------------------------------------------------------------------------
extern "C" void kernel_launch(void* const* d_in, const int* in_sizes, int n_in,
                              void* d_out, int out_size) {
    const float* t_input = (const float*)d_in[0];
    const float* o_input = (const float*)d_in[1];
    const float* W_t     = (const float*)d_in[2];
    const float* W_o     = (const float*)d_in[3];
    const float* a       = (const float*)d_in[4];
    const int*   adj     = (const int*)d_in[5];
    float* out = (float*)d_out;

    cudaFuncSetAttribute(attn_main, cudaFuncAttributeMaxDynamicSharedMemorySize,
                         SM_TOTAL);

    prep_w<<<1, 256>>>(W_t, W_o, a);
    prep_hoT<<<NO / 32, 256>>>(o_input, W_o, a);
    prep_et<<<NT / 8, 256>>>(t_input);
    prep_max<<<NO / 256, 256>>>();
    prep_abef<<<NT / 256, 256>>>();
    attn_main<<<dim3(NT / BM, KSPLIT), THREADS, SM_TOTAL>>>(adj);
    combine<<<NT * FOUT / 4 / 256, 256>>>(out);
}

// round 11
// speedup vs baseline: 3.7583x; 1.0633x over previous
#include <cuda_runtime.h>
#include <cuda_fp16.h>
#include <math.h>
#include <cstdint>

#define NT   8192
#define NO   8192
#define FIN  256
#define FOUT 64
#define ALPHA 0.2f

#define KSPLIT 2
#define JPC   (NO / KSPLIT)   // 4096
#define BK    128
#define TILES (JPC / BK)      // 32
#define BM    64
#define THREADS 512

#define PBUF  16384           // 64 rows x 256B (fp16 128k)
#define HBUF  16384           // 64 rows x 256B
#define EFBUF 1024
#define SM_TOTAL (2 * PBUF + 2 * HBUF + 2 * EFBUF)  // 67584

// 16B-chunk swizzle within 128B halves: row r, chunk c (0..15)
#define SWC(r, c) ((((c) & 8) | (((c) ^ (r)) & 7)))

// ---- scratch ----
__device__ float  g_wtv[FIN], g_wov[FIN];
__device__ float  g_et[NT], g_eo[NO];
__device__ unsigned g_eomax_u;
__device__ float2 g_AB[NT];
__device__ float2 g_EFI[NO];                 // interleaved (E_j, F_j)
__device__ __align__(16) __half g_hoTh[FOUT * NO];  // h_o^T fp16
__device__ float  g_Dp[KSPLIT * NT * FOUT];
__device__ float  g_l[KSPLIT * NT];

// ---- helpers ----
__device__ __forceinline__ uint32_t smem_u32(const void* p) {
    uint32_t a;
    asm("{ .reg .u64 t; cvta.to.shared.u64 t, %1; cvt.u32.u64 %0, t; }" : "=r"(a) : "l"(p));
    return a;
}
__device__ __forceinline__ uint32_t f2h2(float lo, float hi) {
    __half2 h = __floats2half2_rn(lo, hi);
    return *(uint32_t*)&h;
}
__device__ __forceinline__ unsigned fenc(float x) {
    int s = __float_as_int(x);
    return (s < 0) ? ~(unsigned)s : ((unsigned)s | 0x80000000u);
}
__device__ __forceinline__ float fdec(unsigned u) {
    int s = (u & 0x80000000u) ? (int)(u & 0x7fffffffu) : (int)~u;
    return __int_as_float(s);
}
__device__ __forceinline__ void ldm_x4(uint32_t& r0, uint32_t& r1, uint32_t& r2,
                                       uint32_t& r3, uint32_t addr) {
    asm volatile("ldmatrix.sync.aligned.m8n8.x4.shared.b16 {%0,%1,%2,%3}, [%4];"
                 : "=r"(r0), "=r"(r1), "=r"(r2), "=r"(r3) : "r"(addr));
}
__device__ __forceinline__ void mma_f16(float* d, uint32_t a0, uint32_t a1,
                                        uint32_t a2, uint32_t a3,
                                        uint32_t b0, uint32_t b1) {
    asm volatile(
        "mma.sync.aligned.m16n8k16.row.col.f32.f16.f16.f32 "
        "{%0,%1,%2,%3}, {%4,%5,%6,%7}, {%8,%9}, {%0,%1,%2,%3};"
        : "+f"(d[0]), "+f"(d[1]), "+f"(d[2]), "+f"(d[3])
        : "r"(a0), "r"(a1), "r"(a2), "r"(a3), "r"(b0), "r"(b1));
}

// ---------------------------------------------------------------------------
// preps
// ---------------------------------------------------------------------------
__global__ void prep_w(const float* __restrict__ Wt, const float* __restrict__ Wo,
                       const float* __restrict__ a) {
    int k = threadIdx.x;
    if (k == 0) g_eomax_u = 0u;
    float s1 = 0.f, s2 = 0.f;
#pragma unroll
    for (int f = 0; f < FOUT; f++) {
        s1 += Wt[k * FOUT + f] * a[f];
        s2 += Wo[k * FOUT + f] * a[FOUT + f];
    }
    g_wtv[k] = s1;
    g_wov[k] = s2;
}

// h_o = O @ W_o (fp32) -> g_hoTh (fp16, [64][8192]) and g_eo = h_o @ a_o
__global__ __launch_bounds__(256) void prep_hoT(const float* __restrict__ O,
                                                const float* __restrict__ Wo,
                                                const float* __restrict__ a) {
    __shared__ float os[32 * FIN];
    int jb = blockIdx.x * 32, t = threadIdx.x;
    const float4* src = (const float4*)(O + (size_t)jb * FIN);
    float4* dst = (float4*)os;
#pragma unroll
    for (int i = 0; i < 8; i++) dst[t + i * 256] = src[t + i * 256];
    __syncthreads();
    int tj = t >> 5, tc = t & 31;
    float acc[4][2] = {};
#pragma unroll 4
    for (int k = 0; k < FIN; k++) {
        float2 w = *(const float2*)(Wo + k * FOUT + tc * 2);
#pragma unroll
        for (int i = 0; i < 4; i++) {
            float o = os[(tj * 4 + i) * FIN + k];
            acc[i][0] += o * w.x;
            acc[i][1] += o * w.y;
        }
    }
    float ao0 = a[FOUT + tc * 2], ao1 = a[FOUT + tc * 2 + 1];
#pragma unroll
    for (int i = 0; i < 4; i++) {
        float e = acc[i][0] * ao0 + acc[i][1] * ao1;
#pragma unroll
        for (int off = 16; off; off >>= 1) e += __shfl_xor_sync(0xffffffffu, e, off);
        if (tc == 0) g_eo[jb + tj * 4 + i] = e;
    }
#pragma unroll
    for (int ci = 0; ci < 2; ci++) {
        int c = tc * 2 + ci;
        uint2 v = make_uint2(f2h2(acc[0][ci], acc[1][ci]),
                             f2h2(acc[2][ci], acc[3][ci]));
        *(uint2*)(g_hoTh + (size_t)c * NO + jb + tj * 4) = v;
    }
}

__global__ void prep_et(const float* __restrict__ X) {
    int row = blockIdx.x * 8 + (threadIdx.x >> 5);
    int lane = threadIdx.x & 31;
    const float* x = X + (size_t)row * FIN;
    float s = 0.f;
#pragma unroll
    for (int k = lane; k < FIN; k += 32) s += x[k] * g_wtv[k];
#pragma unroll
    for (int off = 16; off; off >>= 1) s += __shfl_xor_sync(0xffffffffu, s, off);
    if (lane == 0) g_et[row] = s;
}

__global__ void prep_max() {
    int i = blockIdx.x * 256 + threadIdx.x;
    float m = g_eo[i];
#pragma unroll
    for (int off = 16; off; off >>= 1)
        m = fmaxf(m, __shfl_xor_sync(0xffffffffu, m, off));
    if ((threadIdx.x & 31) == 0) atomicMax(&g_eomax_u, fenc(m));
}

// A=exp(et-mi), B=exp(.2et-mi), mi=lrelu(et+eomax); E=exp(eo), F=exp(.2eo)
// p_ij = exp(lrelu(et+eo)-mi) = max(A*E, B*F)  in (0,1]
__global__ void prep_abef() {
    int i = blockIdx.x * 256 + threadIdx.x;
    float eomax = fdec(g_eomax_u);
    float et = g_et[i];
    float x0 = et + eomax;
    float mi = fmaxf(x0, ALPHA * x0);
    g_AB[i] = make_float2(expf(et - mi), expf(ALPHA * et - mi));
    float eo = g_eo[i];
    g_EFI[i] = make_float2(expf(eo), expf(ALPHA * eo));
}

// ---------------------------------------------------------------------------
// main: 64 rows x 4096 j per CTA. P (fp16) built exp-free; P@H via
// mma.m16n8k16 fp16; E/F staged in smem; adj prefetched across MMA.
// ---------------------------------------------------------------------------
extern __shared__ char smc[];

__global__ __launch_bounds__(THREADS, 1) void attn_main(const int* __restrict__ adj) {
    const int t = threadIdx.x, w = t >> 5, lane = t & 31;
    const int ibase = blockIdx.x * BM;
    const int split = blockIdx.y;
    const uint32_t sb = smem_u32(smc);

    // P-gen: warp w -> rows w*4..+4; lane jg -> j jg*4..+4
    const int rg = w, jg = lane;
    float2 ABr[4];
#pragma unroll
    for (int rr = 0; rr < 4; rr++) ABr[rr] = g_AB[ibase + rg * 4 + rr];
    const int* adjb = adj + (size_t)(ibase + rg * 4) * NO + split * JPC + jg * 4;
    float lsum[4] = {0.f, 0.f, 0.f, 0.f};

    // H-load: thread -> row hn, chunks hc, hc+8
    const int hn = t >> 3, hc = t & 7;
    const __half* hsrc = g_hoTh + (size_t)hn * NO + split * JPC;

    // EF staging
    const float* efsrc = (const float*)g_EFI + (size_t)split * JPC * 2;
    char* efb0 = smc + 2 * PBUF + 2 * HBUF;

    // MMA: warp -> m16 (rbase) x n16 (cbase)
    const int rbase = (w >> 2) * 16, cbase = (w & 3) * 16;
    const int gid = lane >> 2, tid = lane & 3;
    float acc[2][4] = {};

    // prologue: EF tile 0 + adj tile 0
    if (t < 64) *(float4*)(efb0 + t * 16) = *(const float4*)(efsrc + t * 4);
    int4 aC[4];
#pragma unroll
    for (int rr = 0; rr < 4; rr++) aC[rr] = *(const int4*)(adjb + (size_t)rr * NO);
    __syncthreads();

    for (int tile = 0; tile < TILES; tile++) {
        const int jb = tile * BK;
        const int buf = tile & 1;

        // EF prefetch for next tile (issue LDG early)
        float4 efN;
        if (t < 64 && tile + 1 < TILES)
            efN = *(const float4*)(efsrc + (tile + 1) * BK * 2 + t * 4);

        // ---- P tile (fp16, swizzled) ----
        {
            const char* efb = efb0 + buf * EFBUF;
            float4 ef0 = *(const float4*)(efb + jg * 32);       // E0,F0,E1,F1
            float4 ef1 = *(const float4*)(efb + jg * 32 + 16);  // E2,F2,E3,F3
            char* pB = smc + buf * PBUF;
#pragma unroll
            for (int rr = 0; rr < 4; rr++) {
                const float A = ABr[rr].x, B = ABr[rr].y;
                int4 av = aC[rr];
                float p0 = fmaxf(A * ef0.x, B * ef0.y);
                float p1 = fmaxf(A * ef0.z, B * ef0.w);
                float p2 = fmaxf(A * ef1.x, B * ef1.y);
                float p3 = fmaxf(A * ef1.z, B * ef1.w);
                p0 = __int_as_float(__float_as_int(p0) & (-av.x));
                p1 = __int_as_float(__float_as_int(p1) & (-av.y));
                p2 = __int_as_float(__float_as_int(p2) & (-av.z));
                p3 = __int_as_float(__float_as_int(p3) & (-av.w));
                lsum[rr] += (p0 + p1) + (p2 + p3);
                int r = rg * 4 + rr;
                *(uint2*)(pB + r * 256 + SWC(r, jg >> 1) * 16 + (jg & 1) * 8) =
                    make_uint2(f2h2(p0, p1), f2h2(p2, p3));
            }
        }

        // ---- H tile ----
        {
            char* hB = smc + 2 * PBUF + buf * HBUF;
            uint4 v0 = *(const uint4*)(hsrc + jb + hc * 8);
            uint4 v1 = *(const uint4*)(hsrc + jb + hc * 8 + 64);
            *(uint4*)(hB + hn * 256 + SWC(hn, hc) * 16) = v0;
            *(uint4*)(hB + hn * 256 + SWC(hn, hc + 8) * 16) = v1;
        }

        // ---- EF store for next tile ----
        if (t < 64 && tile + 1 < TILES)
            *(float4*)(efb0 + ((tile + 1) & 1) * EFBUF + t * 16) = efN;
        __syncthreads();

        // ---- adj prefetch (lands during MMA) ----
        int4 aN[4];
        if (tile + 1 < TILES) {
#pragma unroll
            for (int rr = 0; rr < 4; rr++)
                aN[rr] = *(const int4*)(adjb + (size_t)rr * NO + jb + BK);
        }

        // ---- MMA: acc += P[16x128] @ H^T[128x16] per warp ----
        const uint32_t pS = sb + buf * PBUF;
        const uint32_t hS = sb + 2 * PBUF + buf * HBUF;
#pragma unroll
        for (int kk = 0; kk < 8; kk++) {
            uint32_t a0, a1, a2, a3;
            {
                int r = rbase + (lane & 15);
                int c = 2 * kk + (lane >> 4);
                ldm_x4(a0, a1, a2, a3, pS + r * 256 + SWC(r, c) * 16);
            }
            uint32_t b0, b1, b2, b3;
            {
                int g = lane >> 3;
                int n = cbase + (g >> 1) * 8 + (lane & 7);
                int c = 2 * kk + (g & 1);
                ldm_x4(b0, b1, b2, b3, hS + n * 256 + SWC(n, c) * 16);
            }
            mma_f16(acc[0], a0, a1, a2, a3, b0, b1);
            mma_f16(acc[1], a0, a1, a2, a3, b2, b3);
        }

#pragma unroll
        for (int rr = 0; rr < 4; rr++) aC[rr] = aN[rr];
    }

    // ---- epilogue ----
    float* dp = g_Dp + ((size_t)split * NT + ibase) * FOUT;
#pragma unroll
    for (int nt = 0; nt < 2; nt++) {
        int col = cbase + nt * 8 + 2 * tid;
        *(float2*)(dp + (size_t)(rbase + gid) * FOUT + col) =
            make_float2(acc[nt][0], acc[nt][1]);
        *(float2*)(dp + (size_t)(rbase + gid + 8) * FOUT + col) =
            make_float2(acc[nt][2], acc[nt][3]);
    }
#pragma unroll
    for (int rr = 0; rr < 4; rr++) {
        float s = lsum[rr];
#pragma unroll
        for (int off = 16; off; off >>= 1) s += __shfl_xor_sync(0xffffffffu, s, off);
        if (lane == 0) g_l[split * NT + ibase + rg * 4 + rr] = s;
    }
}

// ---------------------------------------------------------------------------
__global__ void combine(float* __restrict__ out) {
    int idx = blockIdx.x * 256 + threadIdx.x;
    int r = idx >> 4, c4 = idx & 15;
    float4 d0 = *(const float4*)(g_Dp + (size_t)r * FOUT + c4 * 4);
    float4 d1 = *(const float4*)(g_Dp + ((size_t)NT + r) * FOUT + c4 * 4);
    float inv = 1.f / (g_l[r] + g_l[NT + r]);
    float v[4] = {(d0.x + d1.x) * inv, (d0.y + d1.y) * inv,
                  (d0.z + d1.z) * inv, (d0.w + d1.w) * inv};
#pragma unroll
    for (int i = 0; i < 4; i++) v[i] = v[i] > 0.f ? v[i] : expm1f(v[i]);
    *(float4*)(out + (size_t)r * FOUT + c4 * 4) = make_float4(v[0], v[1], v[2], v[3]);
}

// ---------------------------------------------------------------------------
extern "C" void kernel_launch(void* const* d_in, const int* in_sizes, int n_in,
                              void* d_out, int out_size) {
    const float* t_input = (const float*)d_in[0];
    const float* o_input = (const float*)d_in[1];
    const float* W_t     = (const float*)d_in[2];
    const float* W_o     = (const float*)d_in[3];
    const float* a       = (const float*)d_in[4];
    const int*   adj     = (const int*)d_in[5];
    float* out = (float*)d_out;

    cudaFuncSetAttribute(attn_main, cudaFuncAttributeMaxDynamicSharedMemorySize,
                         SM_TOTAL);

    prep_w<<<1, 256>>>(W_t, W_o, a);
    prep_hoT<<<NO / 32, 256>>>(o_input, W_o, a);
    prep_et<<<NT / 8, 256>>>(t_input);
    prep_max<<<NO / 256, 256>>>();
    prep_abef<<<NO / 256, 256>>>();
    attn_main<<<dim3(NT / BM, KSPLIT), THREADS, SM_TOTAL>>>(adj);
    combine<<<NT * FOUT / 4 / 256, 256>>>(out);
}

// round 12
// speedup vs baseline: 4.3469x; 1.1566x over previous
#include <cuda_runtime.h>
#include <cuda_fp16.h>
#include <math.h>
#include <cstdint>

#define NT   8192
#define NO   8192
#define FIN  256
#define FOUT 64
#define ALPHA 0.2f

#define KSPLIT 2
#define JPC   (NO / KSPLIT)   // 4096
#define BK    128
#define TILES (JPC / BK)      // 32
#define BM    64
#define THREADS 512

// smem: P 2x16K | H 2x16K | EF 2x1K | ABs 512B
#define PBUF   16384
#define HBUF   16384
#define EFBUF  1024
#define OFF_H  (2 * PBUF)
#define OFF_EF (OFF_H + 2 * HBUF)
#define OFF_AB (OFF_EF + 2 * EFBUF)
#define SM_TOTAL (OFF_AB + 512)          // 68096

// 16B-chunk swizzle within 128B halves: row r, chunk c (0..15)
#define SWC(r, c) ((((c) & 8) | (((c) ^ (r)) & 7)))

// ---- scratch ----
__device__ float  g_wtv[FIN];
__device__ unsigned g_eomax_u;
__device__ float2 g_EFI[NO];                        // interleaved (E_j, F_j)
__device__ __align__(16) __half g_hoTh[FOUT * NO];  // h_o^T fp16
__device__ float  g_Dp[KSPLIT * NT * FOUT];
__device__ float  g_l[KSPLIT * NT];

// ---- helpers ----
__device__ __forceinline__ uint32_t smem_u32(const void* p) {
    uint32_t a;
    asm("{ .reg .u64 t; cvta.to.shared.u64 t, %1; cvt.u32.u64 %0, t; }" : "=r"(a) : "l"(p));
    return a;
}
__device__ __forceinline__ uint32_t f2h2(float lo, float hi) {
    __half2 h = __floats2half2_rn(lo, hi);
    return *(uint32_t*)&h;
}
__device__ __forceinline__ unsigned fenc(float x) {
    int s = __float_as_int(x);
    return (s < 0) ? ~(unsigned)s : ((unsigned)s | 0x80000000u);
}
__device__ __forceinline__ float fdec(unsigned u) {
    int s = (u & 0x80000000u) ? (int)(u & 0x7fffffffu) : (int)~u;
    return __int_as_float(s);
}
__device__ __forceinline__ void ldm_x4(uint32_t& r0, uint32_t& r1, uint32_t& r2,
                                       uint32_t& r3, uint32_t addr) {
    asm volatile("ldmatrix.sync.aligned.m8n8.x4.shared.b16 {%0,%1,%2,%3}, [%4];"
                 : "=r"(r0), "=r"(r1), "=r"(r2), "=r"(r3) : "r"(addr));
}
__device__ __forceinline__ void mma_f16(float* d, uint32_t a0, uint32_t a1,
                                        uint32_t a2, uint32_t a3,
                                        uint32_t b0, uint32_t b1) {
    asm volatile(
        "mma.sync.aligned.m16n8k16.row.col.f32.f16.f16.f32 "
        "{%0,%1,%2,%3}, {%4,%5,%6,%7}, {%8,%9}, {%0,%1,%2,%3};"
        : "+f"(d[0]), "+f"(d[1]), "+f"(d[2]), "+f"(d[3])
        : "r"(a0), "r"(a1), "r"(a2), "r"(a3), "r"(b0), "r"(b1));
}

// ---------------------------------------------------------------------------
// prep_w: wtv = W_t @ a_t; zero eomax
// ---------------------------------------------------------------------------
__global__ void prep_w(const float* __restrict__ Wt, const float* __restrict__ a) {
    int k = threadIdx.x;
    if (k == 0) g_eomax_u = 0u;
    float s1 = 0.f;
#pragma unroll
    for (int f = 0; f < FOUT; f++) s1 += Wt[k * FOUT + f] * a[f];
    g_wtv[k] = s1;
}

// ---------------------------------------------------------------------------
// prep_hoT: h_o^T (fp16) + E/F + eomax, all fused. 32 j-rows per block.
// ---------------------------------------------------------------------------
__global__ __launch_bounds__(256) void prep_hoT(const float* __restrict__ O,
                                                const float* __restrict__ Wo,
                                                const float* __restrict__ a) {
    __shared__ float os[32 * FIN];
    int jb = blockIdx.x * 32, t = threadIdx.x;
    const float4* src = (const float4*)(O + (size_t)jb * FIN);
    float4* dst = (float4*)os;
#pragma unroll
    for (int i = 0; i < 8; i++) dst[t + i * 256] = src[t + i * 256];
    __syncthreads();
    int tj = t >> 5, tc = t & 31;
    float acc[4][2] = {};
#pragma unroll 4
    for (int k = 0; k < FIN; k++) {
        float2 w = *(const float2*)(Wo + k * FOUT + tc * 2);
#pragma unroll
        for (int i = 0; i < 4; i++) {
            float o = os[(tj * 4 + i) * FIN + k];
            acc[i][0] += o * w.x;
            acc[i][1] += o * w.y;
        }
    }
    // eo = h_o @ a_o; E/F; block-local max -> atomic
    float ao0 = a[FOUT + tc * 2], ao1 = a[FOUT + tc * 2 + 1];
    float emax = -1e30f;
#pragma unroll
    for (int i = 0; i < 4; i++) {
        float e = acc[i][0] * ao0 + acc[i][1] * ao1;
#pragma unroll
        for (int off = 16; off; off >>= 1) e += __shfl_xor_sync(0xffffffffu, e, off);
        if (tc == 0) {
            g_EFI[jb + tj * 4 + i] = make_float2(expf(e), expf(ALPHA * e));
            emax = fmaxf(emax, e);
        }
    }
    if (tc == 0) atomicMax(&g_eomax_u, fenc(emax));
    // h_o^T fp16
#pragma unroll
    for (int ci = 0; ci < 2; ci++) {
        int c = tc * 2 + ci;
        uint2 v = make_uint2(f2h2(acc[0][ci], acc[1][ci]),
                             f2h2(acc[2][ci], acc[3][ci]));
        *(uint2*)(g_hoTh + (size_t)c * NO + jb + tj * 4) = v;
    }
}

// ---------------------------------------------------------------------------
// main: 64 rows x 4096 j. AB computed in prologue. Deep register pipeline:
// all LDGs issued one full tile before their smem store / use.
// ---------------------------------------------------------------------------
extern __shared__ char smc[];

__global__ __launch_bounds__(THREADS, 1) void attn_main(const int* __restrict__ adj,
                                                        const float* __restrict__ t_input) {
    const int t = threadIdx.x, w = t >> 5, lane = t & 31;
    const int ibase = blockIdx.x * BM;
    const int split = blockIdx.y;
    const uint32_t sb = smem_u32(smc);
    float2* ABs = (float2*)(smc + OFF_AB);

    // ---- prologue: A_i/B_i for this CTA's 64 rows ----
    {
        int r8 = t >> 3, s8 = t & 7;
        const float* xr = t_input + (size_t)(ibase + r8) * FIN + s8 * 32;
        float s = 0.f;
#pragma unroll
        for (int q = 0; q < 8; q++) {
            float4 x = *(const float4*)(xr + q * 4);
            float4 wv = *(const float4*)(g_wtv + s8 * 32 + q * 4);
            s += x.x * wv.x + x.y * wv.y + x.z * wv.z + x.w * wv.w;
        }
        s += __shfl_xor_sync(0xffffffffu, s, 1);
        s += __shfl_xor_sync(0xffffffffu, s, 2);
        s += __shfl_xor_sync(0xffffffffu, s, 4);
        if (s8 == 0) {
            float eomax = fdec(g_eomax_u);
            float x0 = s + eomax;
            float mi = fmaxf(x0, ALPHA * x0);
            ABs[r8] = make_float2(expf(s - mi), expf(ALPHA * s - mi));
        }
    }

    // P-gen: warp w -> rows w*4..+4; lane -> j lane*4..+4
    const int rg = w, jg = lane;
    const int* adjb = adj + (size_t)(ibase + rg * 4) * NO + split * JPC + jg * 4;

    // H-load: thread -> row hn, chunks hc, hc+8
    const int hn = t >> 3, hc = t & 7;
    const __half* hsrc = g_hoTh + (size_t)hn * NO + split * JPC;
    const float* efsrc = (const float*)g_EFI + (size_t)split * JPC * 2;

    // MMA: warp -> m16 (rbase) x n16 (cbase)
    const int rbase = (w >> 2) * 16, cbase = (w & 3) * 16;
    const int gid = lane >> 2, tid = lane & 3;
    const uint32_t bOne = 0x3C003C00u;  // half2(1,1)
    float acc[2][4] = {};
    float acc_l[4] = {};

    // ---- pipeline prologue ----
    // tile0 H/EF -> smem buf0; tile1 H/EF -> regs; tile0 adj -> regs
    {
        uint4 v0 = *(const uint4*)(hsrc + hc * 8);
        uint4 v1 = *(const uint4*)(hsrc + hc * 8 + 64);
        char* hB = smc + OFF_H;
        *(uint4*)(hB + hn * 256 + SWC(hn, hc) * 16) = v0;
        *(uint4*)(hB + hn * 256 + SWC(hn, hc + 8) * 16) = v1;
    }
    if (t < 64) *(float4*)(smc + OFF_EF + t * 16) = *(const float4*)(efsrc + t * 4);
    uint4 hC0, hC1;
    hC0 = *(const uint4*)(hsrc + BK + hc * 8);
    hC1 = *(const uint4*)(hsrc + BK + hc * 8 + 64);
    float4 efC = make_float4(0.f, 0.f, 0.f, 0.f);
    if (t < 64) efC = *(const float4*)(efsrc + BK * 2 + t * 4);
    int4 aC[4];
#pragma unroll
    for (int rr = 0; rr < 4; rr++)
        aC[rr] = __ldcs((const int4*)(adjb + (size_t)rr * NO));
    __syncthreads();

    float2 ABr[4];
#pragma unroll
    for (int rr = 0; rr < 4; rr++) ABr[rr] = ABs[rg * 4 + rr];

    for (int tile = 0; tile < TILES; tile++) {
        const int jb = tile * BK;
        const int buf = tile & 1;

        // ---- issue all prefetches first (max latency cover) ----
        int4 aN[4];
        if (tile + 1 < TILES) {
#pragma unroll
            for (int rr = 0; rr < 4; rr++)
                aN[rr] = __ldcs((const int4*)(adjb + (size_t)rr * NO + jb + BK));
        }
        uint4 hN0, hN1;
        float4 efN;
        if (tile + 2 < TILES) {
            hN0 = *(const uint4*)(hsrc + jb + 2 * BK + hc * 8);
            hN1 = *(const uint4*)(hsrc + jb + 2 * BK + hc * 8 + 64);
            if (t < 64) efN = *(const float4*)(efsrc + (tile + 2) * BK * 2 + t * 4);
        }

        // ---- P tile (fp16, swizzled) from aC + EF smem ----
        {
            const char* efb = smc + OFF_EF + buf * EFBUF;
            float4 ef0 = *(const float4*)(efb + jg * 32);
            float4 ef1 = *(const float4*)(efb + jg * 32 + 16);
            char* pB = smc + buf * PBUF;
#pragma unroll
            for (int rr = 0; rr < 4; rr++) {
                const float A = ABr[rr].x, B = ABr[rr].y;
                int4 av = aC[rr];
                float p0 = fmaxf(A * ef0.x, B * ef0.y);
                float p1 = fmaxf(A * ef0.z, B * ef0.w);
                float p2 = fmaxf(A * ef1.x, B * ef1.y);
                float p3 = fmaxf(A * ef1.z, B * ef1.w);
                p0 = __int_as_float(__float_as_int(p0) & (-av.x));
                p1 = __int_as_float(__float_as_int(p1) & (-av.y));
                p2 = __int_as_float(__float_as_int(p2) & (-av.z));
                p3 = __int_as_float(__float_as_int(p3) & (-av.w));
                int r = rg * 4 + rr;
                *(uint2*)(pB + r * 256 + SWC(r, jg >> 1) * 16 + (jg & 1) * 8) =
                    make_uint2(f2h2(p0, p1), f2h2(p2, p3));
            }
        }

        // ---- store next tile's H/EF (regs loaded last iteration) ----
        if (tile + 1 < TILES) {
            char* hB = smc + OFF_H + (buf ^ 1) * HBUF;
            *(uint4*)(hB + hn * 256 + SWC(hn, hc) * 16) = hC0;
            *(uint4*)(hB + hn * 256 + SWC(hn, hc + 8) * 16) = hC1;
            if (t < 64) *(float4*)(smc + OFF_EF + (buf ^ 1) * EFBUF + t * 16) = efC;
        }
        __syncthreads();

        // ---- MMA(t): acc += P[16x128] @ H^T[128x16]; ones-col rowsum ----
        const uint32_t pS = sb + buf * PBUF;
        const uint32_t hS = sb + OFF_H + buf * HBUF;
#pragma unroll
        for (int kk = 0; kk < 8; kk++) {
            uint32_t a0, a1, a2, a3;
            {
                int r = rbase + (lane & 15);
                int c = 2 * kk + (lane >> 4);
                ldm_x4(a0, a1, a2, a3, pS + r * 256 + SWC(r, c) * 16);
            }
            uint32_t b0, b1, b2, b3;
            {
                int g = lane >> 3;
                int n = cbase + (g >> 1) * 8 + (lane & 7);
                int c = 2 * kk + (g & 1);
                ldm_x4(b0, b1, b2, b3, hS + n * 256 + SWC(n, c) * 16);
            }
            mma_f16(acc[0], a0, a1, a2, a3, b0, b1);
            mma_f16(acc[1], a0, a1, a2, a3, b2, b3);
            if ((w & 3) == 0) mma_f16(acc_l, a0, a1, a2, a3, bOne, bOne);
        }

        // rotate pipeline regs
#pragma unroll
        for (int rr = 0; rr < 4; rr++) aC[rr] = aN[rr];
        hC0 = hN0; hC1 = hN1; efC = efN;
    }

    // ---- epilogue ----
    float* dp = g_Dp + ((size_t)split * NT + ibase) * FOUT;
#pragma unroll
    for (int nt = 0; nt < 2; nt++) {
        int col = cbase + nt * 8 + 2 * tid;
        *(float2*)(dp + (size_t)(rbase + gid) * FOUT + col) =
            make_float2(acc[nt][0], acc[nt][1]);
        *(float2*)(dp + (size_t)(rbase + gid + 8) * FOUT + col) =
            make_float2(acc[nt][2], acc[nt][3]);
    }
    if ((w & 3) == 0 && tid == 0) {
        g_l[split * NT + ibase + rbase + gid] = acc_l[0];
        g_l[split * NT + ibase + rbase + gid + 8] = acc_l[2];
    }
}

// ---------------------------------------------------------------------------
__global__ void combine(float* __restrict__ out) {
    int idx = blockIdx.x * 256 + threadIdx.x;
    int r = idx >> 4, c4 = idx & 15;
    float4 d0 = *(const float4*)(g_Dp + (size_t)r * FOUT + c4 * 4);
    float4 d1 = *(const float4*)(g_Dp + ((size_t)NT + r) * FOUT + c4 * 4);
    float inv = 1.f / (g_l[r] + g_l[NT + r]);
    float v[4] = {(d0.x + d1.x) * inv, (d0.y + d1.y) * inv,
                  (d0.z + d1.z) * inv, (d0.w + d1.w) * inv};
#pragma unroll
    for (int i = 0; i < 4; i++) v[i] = v[i] > 0.f ? v[i] : expm1f(v[i]);
    *(float4*)(out + (size_t)r * FOUT + c4 * 4) = make_float4(v[0], v[1], v[2], v[3]);
}

// ---------------------------------------------------------------------------
extern "C" void kernel_launch(void* const* d_in, const int* in_sizes, int n_in,
                              void* d_out, int out_size) {
    const float* t_input = (const float*)d_in[0];
    const float* o_input = (const float*)d_in[1];
    const float* W_t     = (const float*)d_in[2];
    const float* W_o     = (const float*)d_in[3];
    const float* a       = (const float*)d_in[4];
    const int*   adj     = (const int*)d_in[5];
    float* out = (float*)d_out;

    cudaFuncSetAttribute(attn_main, cudaFuncAttributeMaxDynamicSharedMemorySize,
                         SM_TOTAL);

    prep_w<<<1, 256>>>(W_t, a);
    prep_hoT<<<NO / 32, 256>>>(o_input, W_o, a);
    attn_main<<<dim3(NT / BM, KSPLIT), THREADS, SM_TOTAL>>>(adj, t_input);
    combine<<<NT * FOUT / 4 / 256, 256>>>(out);
}